// round 2
// baseline (speedup 1.0000x reference)
#include <cuda_runtime.h>
#include <cuda_bf16.h>

// Problem constants
#define Bsz   128
#define Tlen  80
#define Edim  100
#define Udim  512

// Persistent-kernel launch shape
#define NCTA  128
#define NTHR  128
#define PADK  516           // padded K stride (floats) for conflict-free LDS

// Shared memory layout (float offsets) for rnn_kernel
#define OFF_WA 0                          // 64 cols x PADK   (phase-A weight slice)
#define OFF_WB (64 * PADK)                // 32 cols x PADK   (phase-B weight slice)
#define OFF_H  (OFF_WB + 32 * PADK)       // 16 rows x PADK   (h / h0 tile)
#define SMEM_FLOATS (OFF_H + 16 * PADK)
#define SMEM_BYTES  (SMEM_FLOATS * 4)     // 231168 B <= 232448 B max dyn smem

typedef unsigned long long u64;

// Device-global scratch (no cudaMalloc allowed)
__device__ float g_P0[Tlen * Bsz * Udim];   // x@k0 + b0 for all steps (20 MB)
__device__ float g_h [Bsz * Udim];          // carried hidden state
__device__ float g_h0[Bsz * Udim];          // cell-0 output this step
__device__ float g_r1[Bsz * Udim];          // h @ rk1 + b1 this step
__device__ unsigned g_arrive;
__device__ unsigned g_epoch;

// ---------------- helpers ----------------

__device__ __forceinline__ u64 ffma2(u64 a, u64 b, u64 c) {
    u64 d;
    asm("fma.rn.f32x2 %0, %1, %2, %3;" : "=l"(d) : "l"(a), "l"(b), "l"(c));
    return d;
}

__device__ __forceinline__ float fsum(u64 v) {
    float lo, hi;
    asm("mov.b64 {%0, %1}, %2;" : "=f"(lo), "=f"(hi) : "l"(v));
    return lo + hi;
}

// accurate-enough tanh: 1 - 2/(e^{2x}+1); exact saturation at +/-inf behavior
__device__ __forceinline__ float tanh_fast(float x) {
    float e = __expf(2.0f * x);
    return 1.0f - __fdividef(2.0f, e + 1.0f);
}

// Epoch grid barrier. All NCTA CTAs are co-resident (1 CTA/SM, NCTA <= #SMs).
__device__ __forceinline__ void gbar(unsigned &ep) {
    __syncthreads();
    if (threadIdx.x == 0) {
        __threadfence();                               // release my CTA's writes
        unsigned cnt = atomicAdd(&g_arrive, 1u) + 1u;
        unsigned target = ep + 1u;
        if (cnt == NCTA) {
            g_arrive = 0;
            __threadfence();
            atomicExch(&g_epoch, target);              // release
        } else {
            while (*(volatile unsigned*)&g_epoch != target) { }
            __threadfence();                           // acquire
        }
    }
    ep = ep + 1u;
    __syncthreads();
}

// Load 16 rows x 512 cols of src (rows r0..r0+15) into padded SMEM tile.
__device__ __forceinline__ void load_ht(float* HT, const float* src, int r0) {
    const float4* s = (const float4*)(src + r0 * Udim);
#pragma unroll
    for (int i = 0; i < 16; i++) {
        int e = threadIdx.x + i * NTHR;      // 0..2047
        int r = e >> 7, kq = e & 127;
        *(float4*)(HT + r * PADK + (kq << 2)) = s[e];
    }
}

// ---------------- kernel 1: precompute P0 = emb[tokens] @ k0 + b0 ----------------

#define PC_PAIRS 16

__global__ void __launch_bounds__(NTHR) pre_kernel(
    const int* __restrict__ tokens, const float* __restrict__ emb,
    const float* __restrict__ k0, const float* __restrict__ b0)
{
    __shared__ int    tok[PC_PAIRS];
    __shared__ float2 xs2[PC_PAIRS][Edim];   // pre-splatted x values (12.8 KB)

    const int tid = threadIdx.x;

    // first 64 blocks also zero g_h (128*512 floats)
    if (blockIdx.x < 64) {
        int base = blockIdx.x * 1024 + tid * 8;
        float4 z = make_float4(0.f, 0.f, 0.f, 0.f);
        *(float4*)(g_h + base)     = z;
        *(float4*)(g_h + base + 4) = z;
    }

    const int pbase = blockIdx.x * PC_PAIRS;    // pair id = b*Tlen + t
    if (tid < PC_PAIRS) tok[tid] = tokens[pbase + tid];
    __syncthreads();

    for (int e = tid; e < PC_PAIRS * Edim; e += NTHR) {
        int p = e / Edim, k = e - p * Edim;
        float v = emb[tok[p] * Edim + k];
        xs2[p][k] = make_float2(v, v);
    }
    __syncthreads();

    const int u = tid * 4;                       // this thread's 4 output cols
    u64 acc[PC_PAIRS][2];
#pragma unroll
    for (int p = 0; p < PC_PAIRS; p++) { acc[p][0] = 0ull; acc[p][1] = 0ull; }

    for (int k = 0; k < Edim; k++) {
        ulonglong2 wv = *(const ulonglong2*)(k0 + k * Udim + u);
#pragma unroll
        for (int p = 0; p < PC_PAIRS; p++) {
            u64 x2 = *(const u64*)&xs2[p][k];    // uniform LDS.64 broadcast
            acc[p][0] = ffma2(x2, wv.x, acc[p][0]);
            acc[p][1] = ffma2(x2, wv.y, acc[p][1]);
        }
    }

    float4 bv = *(const float4*)(b0 + u);
#pragma unroll
    for (int p = 0; p < PC_PAIRS; p++) {
        int pi = pbase + p;
        int b = pi / Tlen;
        int t = pi - b * Tlen;
        float2 lo, hi;
        asm("mov.b64 {%0, %1}, %2;" : "=f"(lo.x), "=f"(lo.y) : "l"(acc[p][0]));
        asm("mov.b64 {%0, %1}, %2;" : "=f"(hi.x), "=f"(hi.y) : "l"(acc[p][1]));
        float4 o = make_float4(lo.x + bv.x, lo.y + bv.y, hi.x + bv.z, hi.y + bv.w);
        *(float4*)(g_P0 + ((t * Bsz) + b) * Udim + u) = o;
    }
}

// ---------------- kernel 2: persistent scan ----------------
// CTA (g,j): g = rows r0=16g..+15 ; j = col group.
// Phase A: cols j*64..+63 of [rk0 | rk1] (j<8 -> rk0 half -> h0 ; j>=8 -> rk1 half -> r1)
// Phase B: cols j*32..+31 of k1 -> h1 (= next h)

__global__ void __launch_bounds__(NTHR, 1) rnn_kernel(
    const float* __restrict__ rk0, const float* __restrict__ rk1,
    const float* __restrict__ k1,  const float* __restrict__ b1,
    const float* __restrict__ wd,  const float* __restrict__ bd,
    float* __restrict__ out)
{
    extern __shared__ float sm[];
    const int tid  = threadIdx.x;
    const int g    = blockIdx.x >> 4;
    const int j    = blockIdx.x & 15;
    const int r0   = g * 16;
    const int w    = tid >> 5;
    const int lane = tid & 31;

    unsigned ep = 0;
    if (tid == 0) ep = *(volatile unsigned*)&g_epoch;

    // --- load weight slices into SMEM (once) ---
    const float* wsrcA = (j < 8) ? rk0 : rk1;
    const int cbaseA = (j & 7) * 64;
    for (int e = tid; e < 64 * Udim; e += NTHR) {
        int k = e >> 6, cc = e & 63;
        sm[OFF_WA + cc * PADK + k] = wsrcA[k * Udim + cbaseA + cc];
    }
    const int cbaseB = j * 32;
    for (int e = tid; e < 32 * Udim; e += NTHR) {
        int k = e >> 5, cc = e & 31;
        sm[OFF_WB + cc * PADK + k] = k1[k * Udim + cbaseB + cc];
    }
    float b1a = 0.f, b1b = 0.f;
    if (j >= 8) { b1a = b1[cbaseA + lane]; b1b = b1[cbaseA + lane + 32]; }
    __syncthreads();

    const float* hb  = sm + OFF_H + (w * 4) * PADK;    // this warp's 4 rows
    const float* wc1 = sm + OFF_WA + lane * PADK;      // col lane
    const float* wc2 = wc1 + 32 * PADK;                // col lane+32
    const float* wcb = sm + OFF_WB + lane * PADK;      // phase-B col lane

    for (int t = 0; t < Tlen; t++) {
        // ================= Phase A: h @ [rk0|rk1] =================
        load_ht(sm + OFF_H, g_h, r0);
        __syncthreads();

        u64 acc[4][2];
#pragma unroll
        for (int i = 0; i < 4; i++) { acc[i][0] = 0ull; acc[i][1] = 0ull; }

#pragma unroll 4
        for (int k = 0; k < Udim; k += 4) {
            ulonglong2 W1 = *(const ulonglong2*)(wc1 + k);
            ulonglong2 W2 = *(const ulonglong2*)(wc2 + k);
#pragma unroll
            for (int i = 0; i < 4; i++) {
                ulonglong2 H = *(const ulonglong2*)(hb + i * PADK + k);
                acc[i][0] = ffma2(H.x, W1.x, acc[i][0]);
                acc[i][1] = ffma2(H.x, W2.x, acc[i][1]);
                acc[i][0] = ffma2(H.y, W1.y, acc[i][0]);
                acc[i][1] = ffma2(H.y, W2.y, acc[i][1]);
            }
        }

        if (j < 8) {
            const int c1 = cbaseA + lane;                 // global h0 col
#pragma unroll
            for (int i = 0; i < 4; i++) {
                int row = r0 + w * 4 + i;
                const float* p0 = g_P0 + ((t * Bsz) + row) * Udim;
                float s1 = fsum(acc[i][0]) + p0[c1];
                float s2 = fsum(acc[i][1]) + p0[c1 + 32];
                g_h0[row * Udim + c1]      = tanh_fast(s1);
                g_h0[row * Udim + c1 + 32] = tanh_fast(s2);
            }
        } else {
            const int c1 = cbaseA + lane;                 // rk1 col
#pragma unroll
            for (int i = 0; i < 4; i++) {
                int row = r0 + w * 4 + i;
                g_r1[row * Udim + c1]      = fsum(acc[i][0]) + b1a;
                g_r1[row * Udim + c1 + 32] = fsum(acc[i][1]) + b1b;
            }
        }
        gbar(ep);

        // ================= Phase B: h0 @ k1 =================
        load_ht(sm + OFF_H, g_h0, r0);
        __syncthreads();

        u64 acc2[4];
#pragma unroll
        for (int i = 0; i < 4; i++) acc2[i] = 0ull;

#pragma unroll 4
        for (int k = 0; k < Udim; k += 4) {
            ulonglong2 W = *(const ulonglong2*)(wcb + k);
#pragma unroll
            for (int i = 0; i < 4; i++) {
                ulonglong2 H = *(const ulonglong2*)(hb + i * PADK + k);
                acc2[i] = ffma2(H.x, W.x, acc2[i]);
                acc2[i] = ffma2(H.y, W.y, acc2[i]);
            }
        }

        {
            const int c = cbaseB + lane;
#pragma unroll
            for (int i = 0; i < 4; i++) {
                int row = r0 + w * 4 + i;
                float s = fsum(acc2[i]) + g_r1[row * Udim + c];
                g_h[row * Udim + c] = tanh_fast(s);
            }
        }
        gbar(ep);
    }

    // ---- output head: sigmoid(h @ wd + bd), block 0 only ----
    if (blockIdx.x == 0) {
        int row = tid;                                   // 128 threads = 128 rows
        const float4* hv = (const float4*)(g_h + row * Udim);
        const float4* wv = (const float4*)wd;
        float s = bd[0];
#pragma unroll 8
        for (int q = 0; q < Udim / 4; q++) {
            float4 a = hv[q], b = wv[q];
            s += a.x * b.x + a.y * b.y + a.z * b.z + a.w * b.w;
        }
        out[row] = 1.0f / (1.0f + __expf(-s));
    }
}

// ---------------- launch ----------------

extern "C" void kernel_launch(void* const* d_in, const int* in_sizes, int n_in,
                              void* d_out, int out_size) {
    const int*   tokens = (const int*)  d_in[0];
    const float* emb    = (const float*)d_in[1];
    const float* k0     = (const float*)d_in[2];
    const float* rk0    = (const float*)d_in[3];
    const float* b0     = (const float*)d_in[4];
    const float* k1     = (const float*)d_in[5];
    const float* rk1    = (const float*)d_in[6];
    const float* b1     = (const float*)d_in[7];
    const float* wd     = (const float*)d_in[8];
    const float* bd     = (const float*)d_in[9];
    float* out = (float*)d_out;

    (void)in_sizes; (void)n_in; (void)out_size;

    cudaFuncSetAttribute(rnn_kernel, cudaFuncAttributeMaxDynamicSharedMemorySize, SMEM_BYTES);

    pre_kernel<<<(Bsz * Tlen) / PC_PAIRS, NTHR>>>(tokens, emb, k0, b0);
    rnn_kernel<<<NCTA, NTHR, SMEM_BYTES>>>(rk0, rk1, k1, b1, wd, bd, out);
}

// round 3
// speedup vs baseline: 1.1590x; 1.1590x over previous
#include <cuda_runtime.h>
#include <cuda_bf16.h>

// Problem constants
#define Bsz   128
#define Tlen  80
#define Edim  100
#define Udim  512

// Launch shape: 4 independent row-groups x 32 col-slice CTAs
#define NCTA  128
#define NTHR  128
#define GSZ   32            // CTAs per sync group (share one 32-row block)
#define NGRP  4
#define RPC   32            // rows per CTA
#define PADK  516           // padded K stride (conflict-free: 516/4=129 odd)

// SMEM layout (float offsets)
#define OFF_WA 0                          // 32 cols x PADK (phase-A slice)
#define OFF_WB (32 * PADK)                // 16 cols x PADK (phase-B slice)
#define OFF_H  (OFF_WB + 16 * PADK)       // 32 rows x PADK (h/h0 tile)
#define SMEM_FLOATS (OFF_H + RPC * PADK)
#define SMEM_BYTES  (SMEM_FLOATS * 4)     // 165120 B

typedef unsigned long long u64;

// Device-global scratch (no cudaMalloc allowed)
__device__ float g_P0[Tlen * Bsz * Udim];   // x@k0 + b0 for all steps
__device__ float g_h [Bsz * Udim];
__device__ float g_h0[Bsz * Udim];
__device__ float g_r1[Bsz * Udim];
__device__ unsigned g_ctr[NGRP * 128];      // one counter per group, 512B apart

// ---------------- helpers ----------------

__device__ __forceinline__ u64 ffma2(u64 a, u64 b, u64 c) {
    u64 d;
    asm("fma.rn.f32x2 %0, %1, %2, %3;" : "=l"(d) : "l"(a), "l"(b), "l"(c));
    return d;
}

__device__ __forceinline__ float fsum(u64 v) {
    float lo, hi;
    asm("mov.b64 {%0, %1}, %2;" : "=f"(lo), "=f"(hi) : "l"(v));
    return lo + hi;
}

__device__ __forceinline__ float tanh_fast(float x) {
    float e = __expf(2.0f * x);
    return 1.0f - __fdividef(2.0f, e + 1.0f);
}

// Group barrier: monotonic counter, release-red arrive + acquire-load poll.
// No threadfence -> no CCTL.IVALL L1 flush. Cross-CTA data uses __ldcg.
__device__ __forceinline__ void gbar(unsigned* ctr, unsigned target) {
    __syncthreads();
    if (threadIdx.x == 0) {
        asm volatile("red.release.gpu.global.add.u32 [%0], %1;"
                     :: "l"(ctr), "r"(1u) : "memory");
        unsigned v;
        do {
            asm volatile("ld.acquire.gpu.global.u32 %0, [%1];"
                         : "=r"(v) : "l"(ctr) : "memory");
        } while (v < target);
    }
    __syncthreads();
}

// Load 32 rows x 512 cols (this group's rows) into padded SMEM tile (L2-only loads).
__device__ __forceinline__ void load_ht(float* HT, const float* src) {
    const float4* s = (const float4*)src;
#pragma unroll
    for (int i = 0; i < 32; i++) {
        int e = threadIdx.x + i * NTHR;      // 0..4095
        int r = e >> 7, kq = e & 127;
        float4 v = __ldcg(s + e);
        *(float4*)(HT + r * PADK + (kq << 2)) = v;
    }
}

// ---------------- kernel 1: P0 = emb[tokens] @ k0 + b0 ----------------

#define PC_PAIRS 16

__global__ void __launch_bounds__(NTHR) pre_kernel(
    const int* __restrict__ tokens, const float* __restrict__ emb,
    const float* __restrict__ k0, const float* __restrict__ b0)
{
    __shared__ int    tok[PC_PAIRS];
    __shared__ float2 xs2[PC_PAIRS][Edim];

    const int tid = threadIdx.x;

    // reset group barrier counters (fresh every launch / graph replay)
    if (blockIdx.x == 0 && tid < NGRP) g_ctr[tid * 128] = 0;

    // first 64 blocks zero g_h
    if (blockIdx.x < 64) {
        int base = blockIdx.x * 1024 + tid * 8;
        float4 z = make_float4(0.f, 0.f, 0.f, 0.f);
        *(float4*)(g_h + base)     = z;
        *(float4*)(g_h + base + 4) = z;
    }

    const int pbase = blockIdx.x * PC_PAIRS;    // pair id = b*Tlen + t
    if (tid < PC_PAIRS) tok[tid] = tokens[pbase + tid];
    __syncthreads();

    for (int e = tid; e < PC_PAIRS * Edim; e += NTHR) {
        int p = e / Edim, k = e - p * Edim;
        float v = emb[tok[p] * Edim + k];
        xs2[p][k] = make_float2(v, v);
    }
    __syncthreads();

    const int u = tid * 4;
    u64 acc[PC_PAIRS][2];
#pragma unroll
    for (int p = 0; p < PC_PAIRS; p++) { acc[p][0] = 0ull; acc[p][1] = 0ull; }

    for (int k = 0; k < Edim; k++) {
        ulonglong2 wv = *(const ulonglong2*)(k0 + k * Udim + u);
#pragma unroll
        for (int p = 0; p < PC_PAIRS; p++) {
            u64 x2 = *(const u64*)&xs2[p][k];
            acc[p][0] = ffma2(x2, wv.x, acc[p][0]);
            acc[p][1] = ffma2(x2, wv.y, acc[p][1]);
        }
    }

    float4 bv = *(const float4*)(b0 + u);
#pragma unroll
    for (int p = 0; p < PC_PAIRS; p++) {
        int pi = pbase + p;
        int b = pi / Tlen;
        int t = pi - b * Tlen;
        float2 lo, hi;
        asm("mov.b64 {%0, %1}, %2;" : "=f"(lo.x), "=f"(lo.y) : "l"(acc[p][0]));
        asm("mov.b64 {%0, %1}, %2;" : "=f"(hi.x), "=f"(hi.y) : "l"(acc[p][1]));
        float4 o = make_float4(lo.x + bv.x, lo.y + bv.y, hi.x + bv.z, hi.y + bv.w);
        *(float4*)(g_P0 + ((size_t)(t * Bsz) + b) * Udim + u) = o;
    }
}

// ---------------- kernel 2: persistent scan ----------------
// CTA (g, j): g = row group (32 rows), j = col slice.
// Phase A: j<16 -> rk0 cols j*32..+31 (-> h0); j>=16 -> rk1 cols (j-16)*32 (-> r1)
// Phase B: k1 cols j*16..+15 (-> next h)
// Thread tile: 4 rows x 2 cols (A) / 4 rows x 1 col (B); rows = (lane&7) + 8i.

__global__ void __launch_bounds__(NTHR, 1) rnn_kernel(
    const float* __restrict__ rk0, const float* __restrict__ rk1,
    const float* __restrict__ k1,  const float* __restrict__ b1,
    const float* __restrict__ wd,  const float* __restrict__ bd,
    float* __restrict__ out)
{
    extern __shared__ float sm[];
    const int tid  = threadIdx.x;
    const int g    = blockIdx.x >> 5;
    const int j    = blockIdx.x & 31;
    const int r0   = g * RPC;
    const int w    = tid >> 5;
    const int lane = tid & 31;
    const bool isA0 = (j < 16);

    unsigned* ctr = g_ctr + g * 128;
    unsigned nbar = 0;

    // --- load weight slices into SMEM (once), transposed [col][K] ---
    const float* wsrcA = isA0 ? rk0 : rk1;
    const int cbaseA = (j & 15) * 32;
    for (int e = tid; e < 32 * Udim; e += NTHR) {
        int k = e >> 5, cc = e & 31;
        sm[OFF_WA + cc * PADK + k] = wsrcA[k * Udim + cbaseA + cc];
    }
    const int cbaseB = j * 16;
    for (int e = tid; e < 16 * Udim; e += NTHR) {
        int k = e >> 4, cc = e & 15;
        sm[OFF_WB + cc * PADK + k] = k1[k * Udim + cbaseB + cc];
    }

    // thread-tile column indices
    const int c0 = w * 8 + ((lane >> 3) << 1);     // phase A: cols c0, c0+1
    const int cB = w * 4 + (lane >> 3);            // phase B: col cB

    float b1v0 = 0.f, b1v1 = 0.f;
    if (!isA0) { b1v0 = b1[cbaseA + c0]; b1v1 = b1[cbaseA + c0 + 1]; }
    __syncthreads();

    const float* wa0 = sm + OFF_WA + c0 * PADK;
    const float* wa1 = wa0 + PADK;
    const float* wbB = sm + OFF_WB + cB * PADK;
    const int lrb = lane & 7;                      // row base; rows lrb + 8i

    for (int t = 0; t < Tlen; t++) {
        // ================= Phase A: h @ [rk0 | rk1] =================
        // prefetch P0 (hidden under the FMA loop)
        float pv0[4], pv1[4];
        if (isA0) {
            const float* p0 = g_P0 + ((size_t)t * Bsz + r0) * Udim + cbaseA + c0;
#pragma unroll
            for (int i = 0; i < 4; i++) {
                pv0[i] = __ldcg(p0 + (lrb + 8 * i) * Udim);
                pv1[i] = __ldcg(p0 + (lrb + 8 * i) * Udim + 1);
            }
        }

        load_ht(sm + OFF_H, g_h + r0 * Udim);
        __syncthreads();

        u64 acc[4][2];
#pragma unroll
        for (int i = 0; i < 4; i++) { acc[i][0] = 0ull; acc[i][1] = 0ull; }

#pragma unroll 4
        for (int k = 0; k < Udim; k += 4) {
            ulonglong2 W0 = *(const ulonglong2*)(wa0 + k);
            ulonglong2 W1 = *(const ulonglong2*)(wa1 + k);
#pragma unroll
            for (int i = 0; i < 4; i++) {
                ulonglong2 H = *(const ulonglong2*)(sm + OFF_H + (lrb + 8 * i) * PADK + k);
                acc[i][0] = ffma2(H.x, W0.x, acc[i][0]);
                acc[i][0] = ffma2(H.y, W0.y, acc[i][0]);
                acc[i][1] = ffma2(H.x, W1.x, acc[i][1]);
                acc[i][1] = ffma2(H.y, W1.y, acc[i][1]);
            }
        }

        if (isA0) {
#pragma unroll
            for (int i = 0; i < 4; i++) {
                int row = r0 + lrb + 8 * i;
                float s0 = fsum(acc[i][0]) + pv0[i];
                float s1 = fsum(acc[i][1]) + pv1[i];
                g_h0[row * Udim + cbaseA + c0]     = tanh_fast(s0);
                g_h0[row * Udim + cbaseA + c0 + 1] = tanh_fast(s1);
            }
        } else {
#pragma unroll
            for (int i = 0; i < 4; i++) {
                int row = r0 + lrb + 8 * i;
                g_r1[row * Udim + cbaseA + c0]     = fsum(acc[i][0]) + b1v0;
                g_r1[row * Udim + cbaseA + c0 + 1] = fsum(acc[i][1]) + b1v1;
            }
        }
        nbar++; gbar(ctr, nbar * GSZ);

        // ================= Phase B: h0 @ k1 =================
        // prefetch r1 (written by group peers in phase A; after barrier)
        float r1v[4];
        {
            const float* r1p = g_r1 + (size_t)r0 * Udim + cbaseB + cB;
#pragma unroll
            for (int i = 0; i < 4; i++) r1v[i] = __ldcg(r1p + (lrb + 8 * i) * Udim);
        }

        load_ht(sm + OFF_H, g_h0 + r0 * Udim);
        __syncthreads();

        u64 acc2[4];
#pragma unroll
        for (int i = 0; i < 4; i++) acc2[i] = 0ull;

#pragma unroll 4
        for (int k = 0; k < Udim; k += 4) {
            ulonglong2 W = *(const ulonglong2*)(wbB + k);
#pragma unroll
            for (int i = 0; i < 4; i++) {
                ulonglong2 H = *(const ulonglong2*)(sm + OFF_H + (lrb + 8 * i) * PADK + k);
                acc2[i] = ffma2(H.x, W.x, acc2[i]);
                acc2[i] = ffma2(H.y, W.y, acc2[i]);
            }
        }

#pragma unroll
        for (int i = 0; i < 4; i++) {
            int row = r0 + lrb + 8 * i;
            float s = fsum(acc2[i]) + r1v[i];
            g_h[row * Udim + cbaseB + cB] = tanh_fast(s);
        }
        nbar++; gbar(ctr, nbar * GSZ);
    }

    // ---- output head: sigmoid(h @ wd + bd). CTA j==0 of each group does
    // its own 32 rows (its barrier only covers its group's rows). ----
    if (j == 0) {
        int row = r0 + (tid >> 2);
        int p   = tid & 3;
        const float4* hv = (const float4*)(g_h + row * Udim + p * 128);
        const float4* wv = (const float4*)(wd + p * 128);
        float s = 0.f;
#pragma unroll 8
        for (int q = 0; q < 32; q++) {
            float4 a = __ldcg(hv + q);
            float4 b = wv[q];
            s += a.x * b.x + a.y * b.y + a.z * b.z + a.w * b.w;
        }
        s += __shfl_xor_sync(0xffffffffu, s, 1);
        s += __shfl_xor_sync(0xffffffffu, s, 2);
        if (p == 0) out[row] = 1.0f / (1.0f + __expf(-(s + bd[0])));
    }
}

// ---------------- launch ----------------

extern "C" void kernel_launch(void* const* d_in, const int* in_sizes, int n_in,
                              void* d_out, int out_size) {
    const int*   tokens = (const int*)  d_in[0];
    const float* emb    = (const float*)d_in[1];
    const float* k0     = (const float*)d_in[2];
    const float* rk0    = (const float*)d_in[3];
    const float* b0     = (const float*)d_in[4];
    const float* k1     = (const float*)d_in[5];
    const float* rk1    = (const float*)d_in[6];
    const float* b1     = (const float*)d_in[7];
    const float* wd     = (const float*)d_in[8];
    const float* bd     = (const float*)d_in[9];
    float* out = (float*)d_out;

    (void)in_sizes; (void)n_in; (void)out_size;

    cudaFuncSetAttribute(rnn_kernel, cudaFuncAttributeMaxDynamicSharedMemorySize, SMEM_BYTES);

    pre_kernel<<<(Bsz * Tlen) / PC_PAIRS, NTHR>>>(tokens, emb, k0, b0);
    rnn_kernel<<<NCTA, NTHR, SMEM_BYTES>>>(rk0, rk1, k1, b1, wd, bd, out);
}

// round 4
// speedup vs baseline: 1.5621x; 1.3477x over previous
#include <cuda_runtime.h>
#include <cuda_bf16.h>

// Problem constants
#define Bsz   128
#define Tlen  80
#define Edim  100
#define Udim  512

// Launch shape: 4 independent row-groups x 32 col-slice CTAs
#define NCTA  128
#define NTHR  128
#define GSZ   32            // CTAs per sync group (share one 32-row block)
#define NGRP  4
#define RPC   32            // rows per CTA group
#define PADK  516           // padded K stride (bank offset 4 per row/col)

#define APAD  40            // phase-A reduction row pad (8*rg+cg banks distinct)
#define BPAD  20            // phase-B reduction row pad (20*rg+cg banks distinct)

// SMEM layout (float offsets)
#define OFF_WA 0                          // 32 cols x PADK (phase-A weight slice)
#define OFF_WB (32 * PADK)                // 16 cols x PADK (phase-B weight slice)
#define OFF_H  (OFF_WB + 16 * PADK)       // 32 rows x PADK (h/h0 tile)
#define OFF_RED (OFF_H + RPC * PADK)      // max(4*32*APAD, 4*32*BPAD) = 5120
#define SMEM_FLOATS (OFF_RED + 4 * 32 * APAD)
#define SMEM_BYTES  (SMEM_FLOATS * 4)     // 185600 B <= 232448

typedef unsigned long long u64;

// Device-global scratch (no cudaMalloc allowed)
__device__ float g_P0[Tlen * Bsz * Udim];   // x@k0 + b0 for all steps
__device__ float g_h [Bsz * Udim];
__device__ float g_h0[Bsz * Udim];
__device__ float g_r1[Bsz * Udim];
__device__ unsigned g_ctr[NGRP * 128];      // one counter per group, 512B apart

// ---------------- helpers ----------------

__device__ __forceinline__ u64 ffma2(u64 a, u64 b, u64 c) {
    u64 d;
    asm("fma.rn.f32x2 %0, %1, %2, %3;" : "=l"(d) : "l"(a), "l"(b), "l"(c));
    return d;
}

__device__ __forceinline__ float fsum(u64 v) {
    float lo, hi;
    asm("mov.b64 {%0, %1}, %2;" : "=f"(lo), "=f"(hi) : "l"(v));
    return lo + hi;
}

__device__ __forceinline__ float tanh_fast(float x) {
    float e = __expf(2.0f * x);
    return 1.0f - __fdividef(2.0f, e + 1.0f);
}

// Group barrier: monotonic counter, release-red arrive + acquire-load poll.
__device__ __forceinline__ void gbar(unsigned* ctr, unsigned target) {
    __syncthreads();
    if (threadIdx.x == 0) {
        asm volatile("red.release.gpu.global.add.u32 [%0], %1;"
                     :: "l"(ctr), "r"(1u) : "memory");
        unsigned v;
        do {
            asm volatile("ld.acquire.gpu.global.u32 %0, [%1];"
                         : "=r"(v) : "l"(ctr) : "memory");
        } while (v < target);
    }
    __syncthreads();
}

// Load 32 rows x 512 cols (this group's rows) into padded SMEM tile (L2-only loads).
__device__ __forceinline__ void load_ht(float* HT, const float* src) {
    const float4* s = (const float4*)src;
#pragma unroll
    for (int i = 0; i < 32; i++) {
        int e = threadIdx.x + i * NTHR;      // 0..4095
        int r = e >> 7, kq = e & 127;
        float4 v = __ldcg(s + e);
        *(float4*)(HT + r * PADK + (kq << 2)) = v;
    }
}

// ---------------- kernel 1: P0 = emb[tokens] @ k0 + b0 ----------------

#define PC_PAIRS 16

__global__ void __launch_bounds__(NTHR) pre_kernel(
    const int* __restrict__ tokens, const float* __restrict__ emb,
    const float* __restrict__ k0, const float* __restrict__ b0)
{
    __shared__ int    tok[PC_PAIRS];
    __shared__ float2 xs2[PC_PAIRS][Edim];

    const int tid = threadIdx.x;

    if (blockIdx.x == 0 && tid < NGRP) g_ctr[tid * 128] = 0;

    if (blockIdx.x < 64) {
        int base = blockIdx.x * 1024 + tid * 8;
        float4 z = make_float4(0.f, 0.f, 0.f, 0.f);
        *(float4*)(g_h + base)     = z;
        *(float4*)(g_h + base + 4) = z;
    }

    const int pbase = blockIdx.x * PC_PAIRS;    // pair id = b*Tlen + t
    if (tid < PC_PAIRS) tok[tid] = tokens[pbase + tid];
    __syncthreads();

    for (int e = tid; e < PC_PAIRS * Edim; e += NTHR) {
        int p = e / Edim, k = e - p * Edim;
        float v = emb[tok[p] * Edim + k];
        xs2[p][k] = make_float2(v, v);
    }
    __syncthreads();

    const int u = tid * 4;
    u64 acc[PC_PAIRS][2];
#pragma unroll
    for (int p = 0; p < PC_PAIRS; p++) { acc[p][0] = 0ull; acc[p][1] = 0ull; }

    for (int k = 0; k < Edim; k++) {
        ulonglong2 wv = *(const ulonglong2*)(k0 + k * Udim + u);
#pragma unroll
        for (int p = 0; p < PC_PAIRS; p++) {
            u64 x2 = *(const u64*)&xs2[p][k];
            acc[p][0] = ffma2(x2, wv.x, acc[p][0]);
            acc[p][1] = ffma2(x2, wv.y, acc[p][1]);
        }
    }

    float4 bv = *(const float4*)(b0 + u);
#pragma unroll
    for (int p = 0; p < PC_PAIRS; p++) {
        int pi = pbase + p;
        int b = pi / Tlen;
        int t = pi - b * Tlen;
        float2 lo, hi;
        asm("mov.b64 {%0, %1}, %2;" : "=f"(lo.x), "=f"(lo.y) : "l"(acc[p][0]));
        asm("mov.b64 {%0, %1}, %2;" : "=f"(hi.x), "=f"(hi.y) : "l"(acc[p][1]));
        float4 o = make_float4(lo.x + bv.x, lo.y + bv.y, hi.x + bv.z, hi.y + bv.w);
        *(float4*)(g_P0 + ((size_t)(t * Bsz) + b) * Udim + u) = o;
    }
}

// ---------------- kernel 2: persistent scan ----------------
// CTA (g, j): g = row group (32 rows), j = col slice.
// K is split across the 4 warps (warp w: k in [128w, 128w+128)); partials
// are reduced through padded SMEM buffers once per phase.
// Phase A: j<16 -> rk0 cols j*32..+31 (-> h0); j>=16 -> rk1 cols (-> r1).
//   thread tile 8 rows x 4 cols: rows rg+4i (rg=lane&3), cols cg+8j (cg=lane>>2)
// Phase B: k1 cols j*16..+15 (-> next h).
//   thread tile 4 rows x 4 cols: rows rgB+8i (rgB=lane&7), cols cgB+4j (cgB=lane>>3)

__global__ void __launch_bounds__(NTHR, 1) rnn_kernel(
    const float* __restrict__ rk0, const float* __restrict__ rk1,
    const float* __restrict__ k1,  const float* __restrict__ b1,
    const float* __restrict__ wd,  const float* __restrict__ bd,
    float* __restrict__ out)
{
    extern __shared__ float sm[];
    const int tid  = threadIdx.x;
    const int g    = blockIdx.x >> 5;
    const int j    = blockIdx.x & 31;
    const int r0   = g * RPC;
    const int w    = tid >> 5;
    const int lane = tid & 31;
    const bool isA0 = (j < 16);

    unsigned* ctr = g_ctr + g * 128;
    unsigned nbar = 0;

    // --- load weight slices into SMEM (once), transposed [col][K] ---
    const float* wsrcA = isA0 ? rk0 : rk1;
    const int cbaseA = (j & 15) * 32;
    for (int e = tid; e < 32 * Udim; e += NTHR) {
        int k = e >> 5, cc = e & 31;
        sm[OFF_WA + cc * PADK + k] = wsrcA[k * Udim + cbaseA + cc];
    }
    const int cbaseB = j * 16;
    for (int e = tid; e < 16 * Udim; e += NTHR) {
        int k = e >> 4, cc = e & 15;
        sm[OFF_WB + cc * PADK + k] = k1[k * Udim + cbaseB + cc];
    }

    // phase-A lane geometry
    const int rg = lane & 3;        // row base (rows rg + 4i, i<8)
    const int cg = lane >> 2;       // col base (cols cg + 8jj, jj<4)
    // phase-B lane geometry
    const int rgB = lane & 7;       // rows rgB + 8i, i<4
    const int cgB = lane >> 3;      // cols cgB + 4jj, jj<4

    // phase-A bias prefetch (rk1 half)
    float b1v[4];
#pragma unroll
    for (int jj = 0; jj < 4; jj++)
        b1v[jj] = isA0 ? 0.f : b1[cbaseA + cg + 8 * jj];
    __syncthreads();

    const float* HpA = sm + OFF_H  + w * 128;
    const float* WpA = sm + OFF_WA + w * 128;
    const float* WpB = sm + OFF_WB + w * 128;
    float* redw  = sm + OFF_RED + w * 32 * APAD;
    float* redwB = sm + OFF_RED + w * 32 * BPAD;

    for (int t = 0; t < Tlen; t++) {
        // ================= Phase A: h @ [rk0 | rk1] =================
        // prefetch P0 for this thread's finalize outputs (rows 2w,2w+1 tiles)
        float pv[2][4];
        if (isA0) {
#pragma unroll
            for (int ii = 0; ii < 2; ii++) {
                int lrow = rg + 4 * (2 * w + ii);
                const float* p0 = g_P0 + ((size_t)t * Bsz + r0 + lrow) * Udim + cbaseA;
#pragma unroll
                for (int jj = 0; jj < 4; jj++)
                    pv[ii][jj] = __ldcg(p0 + cg + 8 * jj);
            }
        }

        load_ht(sm + OFF_H, g_h + r0 * Udim);
        __syncthreads();

        u64 acc[8][4];
#pragma unroll
        for (int i = 0; i < 8; i++)
#pragma unroll
            for (int jj = 0; jj < 4; jj++) acc[i][jj] = 0ull;

#pragma unroll 2
        for (int kc = 0; kc < 32; kc++) {
            const int k = kc * 4;
            ulonglong2 Wv[4];
#pragma unroll
            for (int jj = 0; jj < 4; jj++)
                Wv[jj] = *(const ulonglong2*)(WpA + (cg + 8 * jj) * PADK + k);
#pragma unroll
            for (int i = 0; i < 8; i++) {
                ulonglong2 Hv = *(const ulonglong2*)(HpA + (rg + 4 * i) * PADK + k);
#pragma unroll
                for (int jj = 0; jj < 4; jj++) {
                    acc[i][jj] = ffma2(Hv.x, Wv[jj].x, acc[i][jj]);
                    acc[i][jj] = ffma2(Hv.y, Wv[jj].y, acc[i][jj]);
                }
            }
        }

        // store partials (conflict-free: bank = 8*rg + cg + const)
#pragma unroll
        for (int i = 0; i < 8; i++)
#pragma unroll
            for (int jj = 0; jj < 4; jj++)
                redw[(rg + 4 * i) * APAD + cg + 8 * jj] = fsum(acc[i][jj]);
        __syncthreads();

        // finalize: this thread sums 4 warp-partials for rows i = 2w, 2w+1
#pragma unroll
        for (int ii = 0; ii < 2; ii++) {
            int lrow = rg + 4 * (2 * w + ii);
            int grow = (r0 + lrow) * Udim + cbaseA;
#pragma unroll
            for (int jj = 0; jj < 4; jj++) {
                int lcol = cg + 8 * jj;
                float s = sm[OFF_RED + 0 * 32 * APAD + lrow * APAD + lcol]
                        + sm[OFF_RED + 1 * 32 * APAD + lrow * APAD + lcol]
                        + sm[OFF_RED + 2 * 32 * APAD + lrow * APAD + lcol]
                        + sm[OFF_RED + 3 * 32 * APAD + lrow * APAD + lcol];
                if (isA0) g_h0[grow + lcol] = tanh_fast(s + pv[ii][jj]);
                else      g_r1[grow + lcol] = s + b1v[jj];
            }
        }
        nbar++; gbar(ctr, nbar * GSZ);

        // ================= Phase B: h0 @ k1 =================
        // prefetch r1 for finalize (row rgB + 8w, 4 cols)
        float r1v[4];
        {
            const float* r1p = g_r1 + (size_t)(r0 + rgB + 8 * w) * Udim + cbaseB;
#pragma unroll
            for (int jj = 0; jj < 4; jj++)
                r1v[jj] = __ldcg(r1p + cgB + 4 * jj);
        }

        load_ht(sm + OFF_H, g_h0 + r0 * Udim);
        __syncthreads();

        u64 acc2[4][4];
#pragma unroll
        for (int i = 0; i < 4; i++)
#pragma unroll
            for (int jj = 0; jj < 4; jj++) acc2[i][jj] = 0ull;

#pragma unroll 2
        for (int kc = 0; kc < 32; kc++) {
            const int k = kc * 4;
            ulonglong2 Wv[4];
#pragma unroll
            for (int jj = 0; jj < 4; jj++)
                Wv[jj] = *(const ulonglong2*)(WpB + (cgB + 4 * jj) * PADK + k);
#pragma unroll
            for (int i = 0; i < 4; i++) {
                ulonglong2 Hv = *(const ulonglong2*)(HpA + (rgB + 8 * i) * PADK + k);
#pragma unroll
                for (int jj = 0; jj < 4; jj++) {
                    acc2[i][jj] = ffma2(Hv.x, Wv[jj].x, acc2[i][jj]);
                    acc2[i][jj] = ffma2(Hv.y, Wv[jj].y, acc2[i][jj]);
                }
            }
        }

        // store partials (bank = 20*rgB + cgB + const, distinct)
#pragma unroll
        for (int i = 0; i < 4; i++)
#pragma unroll
            for (int jj = 0; jj < 4; jj++)
                redwB[(rgB + 8 * i) * BPAD + cgB + 4 * jj] = fsum(acc2[i][jj]);
        __syncthreads();

        // finalize: row rgB + 8w, 4 cols
        {
            int lrow = rgB + 8 * w;
            int grow = (r0 + lrow) * Udim + cbaseB;
#pragma unroll
            for (int jj = 0; jj < 4; jj++) {
                int lcol = cgB + 4 * jj;
                float s = sm[OFF_RED + 0 * 32 * BPAD + lrow * BPAD + lcol]
                        + sm[OFF_RED + 1 * 32 * BPAD + lrow * BPAD + lcol]
                        + sm[OFF_RED + 2 * 32 * BPAD + lrow * BPAD + lcol]
                        + sm[OFF_RED + 3 * 32 * BPAD + lrow * BPAD + lcol];
                g_h[grow + lcol] = tanh_fast(s + r1v[jj]);
            }
        }
        nbar++; gbar(ctr, nbar * GSZ);
    }

    // ---- output head: sigmoid(h @ wd + bd), CTA j==0 of each group ----
    if (j == 0) {
        int row = r0 + (tid >> 2);
        int p   = tid & 3;
        const float4* hv = (const float4*)(g_h + row * Udim + p * 128);
        const float4* wv = (const float4*)(wd + p * 128);
        float s = 0.f;
#pragma unroll 8
        for (int q = 0; q < 32; q++) {
            float4 a = __ldcg(hv + q);
            float4 b = wv[q];
            s += a.x * b.x + a.y * b.y + a.z * b.z + a.w * b.w;
        }
        s += __shfl_xor_sync(0xffffffffu, s, 1);
        s += __shfl_xor_sync(0xffffffffu, s, 2);
        if (p == 0) out[row] = 1.0f / (1.0f + __expf(-(s + bd[0])));
    }
}

// ---------------- launch ----------------

extern "C" void kernel_launch(void* const* d_in, const int* in_sizes, int n_in,
                              void* d_out, int out_size) {
    const int*   tokens = (const int*)  d_in[0];
    const float* emb    = (const float*)d_in[1];
    const float* k0     = (const float*)d_in[2];
    const float* rk0    = (const float*)d_in[3];
    const float* b0     = (const float*)d_in[4];
    const float* k1     = (const float*)d_in[5];
    const float* rk1    = (const float*)d_in[6];
    const float* b1     = (const float*)d_in[7];
    const float* wd     = (const float*)d_in[8];
    const float* bd     = (const float*)d_in[9];
    float* out = (float*)d_out;

    (void)in_sizes; (void)n_in; (void)out_size;

    cudaFuncSetAttribute(rnn_kernel, cudaFuncAttributeMaxDynamicSharedMemorySize, SMEM_BYTES);

    pre_kernel<<<(Bsz * Tlen) / PC_PAIRS, NTHR>>>(tokens, emb, k0, b0);
    rnn_kernel<<<NCTA, NTHR, SMEM_BYTES>>>(rk0, rk1, k1, b1, wd, bd, out);
}